// round 9
// baseline (speedup 1.0000x reference)
#include <cuda_runtime.h>
#include <math.h>
#include <stdint.h>

#define HID 512
#define BAT 64
#define SEQ 1024
#define INS 256
#define OUTS 256
#define WROW 768   /* INS + HID */

/* scan partition: 256 CTAs = 16 row-groups x 16 batch-groups (4 batches) */
#define NRG 16
#define NBG 16
#define RPC 32     /* rows per CTA */
#define BPC 4      /* batches per CTA */
#define KCH 8      /* k-chunks (warps) per CTA */
#define KLEN 64    /* k per chunk */
#define SLAB (HID * BPC)          /* floats per group per buffer = 2048 */

#define NCHUNK 8   /* attention seq chunks */
#define CHS (SEQ / NCHUNK)

/* ---------------- static device scratch (no allocations) ------------------ */
__device__ float g_xp[(size_t)SEQ * BAT * HID];    /* x_proj  [s][b][h] */
__device__ float g_hseq[(size_t)BAT * SEQ * HID];  /* hidden  [b][s][h] */
__device__ float g_h[2 * NBG * SLAB];              /* h ping-pong [buf][bg][k][b] */
__device__ unsigned g_cnt[NBG * 1024];             /* per-group counters, 4KB apart */
__device__ float g_sc[BAT * SEQ];                  /* scores / attn weights */
__device__ float g_ctxp[BAT * NCHUNK * HID];       /* context partials */

/* ---------------- f32x2 helpers ------------------------------------------- */
__device__ __forceinline__ unsigned long long f2dup(float a) {
    unsigned long long r;
    asm("mov.b64 %0, {%1, %1};" : "=l"(r) : "f"(a));
    return r;
}
__device__ __forceinline__ void ffma2(unsigned long long& d,
                                      unsigned long long a,
                                      unsigned long long b) {
    asm("fma.rn.f32x2 %0, %1, %2, %0;" : "+l"(d) : "l"(a), "l"(b));
}
__device__ __forceinline__ float2 unpk(unsigned long long a) {
    float2 f;
    asm("mov.b64 {%0, %1}, %2;" : "=f"(f.x), "=f"(f.y) : "l"(a));
    return f;
}
__device__ __forceinline__ unsigned ld_acq(const unsigned* p) {
    unsigned v;
    asm volatile("ld.acquire.gpu.u32 %0, [%1];" : "=r"(v) : "l"(p) : "memory");
    return v;
}
__device__ __forceinline__ void red_rel_add(unsigned* p, unsigned v) {
    asm volatile("red.release.gpu.add.u32 [%0], %1;" :: "l"(p), "r"(v)
                 : "memory");
}

/* ---------------- nop kernel (launch-order padding for ncu) ---------------- */
__global__ void k_nop() {}

/* ---------------- init: zero h ping-pong + barrier words ------------------- */
__global__ void k_init() {
    int tid = blockIdx.x * blockDim.x + threadIdx.x;
    int n = 2 * NBG * SLAB;
    for (int i = tid; i < n; i += gridDim.x * blockDim.x) g_h[i] = 0.0f;
    if (tid < NBG) g_cnt[tid * 1024] = 0u;
}

/* ---------------- GEMM: xp[s][b][h] = sum_i Wx[h][i]*x[b][s][i] + b_ih[h] -- */
#define GKC 32
__global__ void __launch_bounds__(256) k_gemm(const float* __restrict__ x,
                                              const float* __restrict__ W,
                                              const float* __restrict__ bih) {
    __shared__ float wxs[GKC][132];
    __shared__ float xs[GKC][68];
    const int s  = blockIdx.y;
    const int h0 = blockIdx.x * 128;
    const int tid = threadIdx.x;
    const int bg = tid & 7;
    const int hg = tid >> 3;

    unsigned long long acc[4][4];
#pragma unroll
    for (int i = 0; i < 4; i++)
#pragma unroll
        for (int j = 0; j < 4; j++) acc[i][j] = 0ull;

    for (int c = 0; c < INS; c += GKC) {
        {
            int hh = tid >> 1;
            int kk = (tid & 1) * 16;
            const float* src = W + (size_t)(h0 + hh) * WROW + c + kk;
#pragma unroll
            for (int q = 0; q < 4; q++) {
                float4 v = *(const float4*)(src + q * 4);
                wxs[kk + q * 4 + 0][hh] = v.x;
                wxs[kk + q * 4 + 1][hh] = v.y;
                wxs[kk + q * 4 + 2][hh] = v.z;
                wxs[kk + q * 4 + 3][hh] = v.w;
            }
        }
        {
            int bb = tid >> 2;
            int kk = (tid & 3) * 8;
            const float* src = x + ((size_t)bb * SEQ + s) * INS + c + kk;
            float4 a = *(const float4*)(src);
            float4 b4 = *(const float4*)(src + 4);
            xs[kk + 0][bb] = a.x;  xs[kk + 1][bb] = a.y;
            xs[kk + 2][bb] = a.z;  xs[kk + 3][bb] = a.w;
            xs[kk + 4][bb] = b4.x; xs[kk + 5][bb] = b4.y;
            xs[kk + 6][bb] = b4.z; xs[kk + 7][bb] = b4.w;
        }
        __syncthreads();
#pragma unroll 8
        for (int k = 0; k < GKC; k++) {
            float4 w4 = *(const float4*)&wxs[k][hg * 4];
            ulonglong2 xA = *(const ulonglong2*)&xs[k][bg * 8];
            ulonglong2 xB = *(const ulonglong2*)&xs[k][bg * 8 + 4];
            unsigned long long w2[4];
            w2[0] = f2dup(w4.x); w2[1] = f2dup(w4.y);
            w2[2] = f2dup(w4.z); w2[3] = f2dup(w4.w);
#pragma unroll
            for (int hh = 0; hh < 4; hh++) {
                ffma2(acc[hh][0], w2[hh], xA.x);
                ffma2(acc[hh][1], w2[hh], xA.y);
                ffma2(acc[hh][2], w2[hh], xB.x);
                ffma2(acc[hh][3], w2[hh], xB.y);
            }
        }
        __syncthreads();
    }
    float bi[4];
#pragma unroll
    for (int i = 0; i < 4; i++) bi[i] = bih[h0 + hg * 4 + i];
#pragma unroll
    for (int j = 0; j < 4; j++) {
        float2 p[4];
#pragma unroll
        for (int hh = 0; hh < 4; hh++) p[hh] = unpk(acc[hh][j]);
        int blo = bg * 8 + 2 * j;
        float* d0 = g_xp + ((size_t)s * BAT + blo) * HID + h0 + hg * 4;
        float* d1 = d0 + HID;
        *(float4*)d0 = make_float4(p[0].x + bi[0], p[1].x + bi[1],
                                   p[2].x + bi[2], p[3].x + bi[3]);
        *(float4*)d1 = make_float4(p[0].y + bi[0], p[1].y + bi[1],
                                   p[2].y + bi[2], p[3].y + bi[3]);
    }
}

/* ---------------- persistent RNN scan: 2 chains/SM + flat barrier ---------- */
__global__ void __launch_bounds__(256, 2) k_scan(const float* __restrict__ W) {
    __shared__ __align__(16) float h_s[HID][BPC];    /* 8 KB  [k][b] */
    __shared__ float prt[KCH][BPC][RPC];             /* 4 KB  [kc][ob][r] */

    const int tid = threadIdx.x;
    const int rg = blockIdx.x & (NRG - 1);
    const int bg = blockIdx.x >> 4;
    const int h0 = rg * RPC;
    const int b0 = bg * BPC;
    const int kc = tid >> 5;   /* warp = k-chunk */
    const int r  = tid & 31;   /* row in tile */

    /* Wh slice in registers: Wh[h0+r][kc*64 .. +63] */
    float w[KLEN];
    {
        const float4* wp =
            (const float4*)(W + (size_t)(h0 + r) * WROW + INS + kc * KLEN);
#pragma unroll
        for (int q = 0; q < 16; q++) {
            float4 v = wp[q];
            w[4 * q + 0] = v.x; w[4 * q + 1] = v.y;
            w[4 * q + 2] = v.z; w[4 * q + 3] = v.w;
        }
    }

    const int orr = tid & 31;          /* reduce: row    (tid < 128) */
    const int ob  = (tid >> 5) & 3;    /* reduce: batch  (tid < 128) */
    const float* xpp = g_xp + (size_t)(b0 + ob) * HID + (h0 + orr);
    float* hseqp = g_hseq + ((size_t)(b0 + ob) * SEQ) * HID + (h0 + orr);
    unsigned* cnt = &g_cnt[bg * 1024];
    float* const slabA = g_h + (size_t)bg * SLAB;              /* buf 0 */
    float* const slabB = g_h + (size_t)(NBG + bg) * SLAB;      /* buf 1 */

    float xpv = (tid < 128) ? __ldg(xpp) : 0.0f;   /* xp for t = 0 */
    for (int t = 0; t < SEQ; t++) {
        const int buf = t & 1;

        /* prefetch next step's xp (independent of h -> overlaps wait) */
        float xpv_next = 0.0f;
        if (tid < 128 && t + 1 < SEQ)
            xpv_next = __ldg(xpp + (size_t)(t + 1) * BAT * HID);

        /* flat barrier: every CTA polls its group counter */
        if (t > 0) {
            if (tid == 0) {
                unsigned tgt = (unsigned)(NRG * t);
                while (ld_acq(cnt) < tgt) {}
            }
            __syncthreads();
        }

        /* load h_t slab (8 KB contiguous) into smem */
        {
            const float4* src = (const float4*)(buf ? slabB : slabA);
            float4* dst = (float4*)&h_s[0][0];
            dst[tid] = src[tid];
            dst[tid + 256] = src[tid + 256];
        }
        __syncthreads();

        /* matvec partial: warp kc, row r, 4 batches (2 x f32x2) */
        unsigned long long a0 = 0ull, a1 = 0ull;
        const float* hb = &h_s[kc * KLEN][0];
#pragma unroll
        for (int j = 0; j < KLEN; j++) {
            ulonglong2 hv = *(const ulonglong2*)(hb + 4 * j);
            unsigned long long w2 = f2dup(w[j]);
            ffma2(a0, w2, hv.x);
            ffma2(a1, w2, hv.y);
        }
        {
            float2 f0 = unpk(a0), f1 = unpk(a1);
            prt[kc][0][r] = f0.x;
            prt[kc][1][r] = f0.y;
            prt[kc][2][r] = f1.x;
            prt[kc][3][r] = f1.y;
        }
        __syncthreads();

        /* reduce 8 k-chunks + tanh + publish (128 threads, one value each) */
        if (tid < 128) {
            float sum = xpv;
#pragma unroll
            for (int c = 0; c < KCH; c++) sum += prt[c][ob][orr];
            float hv = tanhf(sum);
            float* ns = buf ? slabA : slabB;
            ns[(h0 + orr) * BPC + ob] = hv;      /* L2 exchange slab */
            hseqp[(size_t)t * HID] = hv;          /* hseq (fire and forget) */
        }
        __syncthreads();

        /* arrive: release-RMW orders the slab stores before the flag */
        if (tid == 0) red_rel_add(cnt, 1u);

        xpv = xpv_next;
    }
}

/* ---------------- attention pass 1: scores -------------------------------- */
__global__ void __launch_bounds__(256) k_score() {
    __shared__ float fin[HID];
    const int b  = blockIdx.y;
    const int cs = blockIdx.x;
    const int tid = threadIdx.x;
    const int lane = tid & 31;
    const int wid = tid >> 5;
    const float* hb = g_hseq + (size_t)b * SEQ * HID;

    for (int i = tid; i < HID; i += 256)
        fin[i] = hb[(size_t)(SEQ - 1) * HID + i];
    __syncthreads();

    for (int s0 = wid; s0 < CHS; s0 += 8) {
        int s = cs * CHS + s0;
        const float* row = hb + (size_t)s * HID;
        float p = 0.0f;
#pragma unroll
        for (int q = 0; q < 4; q++) {
            float4 v = *(const float4*)(row + lane * 4 + q * 128);
            float4 f = *(const float4*)(fin + lane * 4 + q * 128);
            p += v.x * f.x + v.y * f.y + v.z * f.z + v.w * f.w;
        }
#pragma unroll
        for (int off = 16; off > 0; off >>= 1)
            p += __shfl_down_sync(0xffffffffu, p, off);
        if (lane == 0) g_sc[(size_t)b * SEQ + s] = p;
    }
}

/* ---------------- attention pass 2: softmax over seq ----------------------- */
__global__ void __launch_bounds__(256) k_softmax() {
    __shared__ float rbuf[256];
    const int b = blockIdx.x;
    const int tid = threadIdx.x;
    float* sc = g_sc + (size_t)b * SEQ;

    float v[4];
#pragma unroll
    for (int q = 0; q < 4; q++) v[q] = sc[tid + q * 256];
    float m = fmaxf(fmaxf(v[0], v[1]), fmaxf(v[2], v[3]));
    rbuf[tid] = m;
    __syncthreads();
    for (int off = 128; off > 0; off >>= 1) {
        if (tid < off) rbuf[tid] = fmaxf(rbuf[tid], rbuf[tid + off]);
        __syncthreads();
    }
    float mx = rbuf[0];
    __syncthreads();
    float ssum = 0.0f;
#pragma unroll
    for (int q = 0; q < 4; q++) { v[q] = expf(v[q] - mx); ssum += v[q]; }
    rbuf[tid] = ssum;
    __syncthreads();
    for (int off = 128; off > 0; off >>= 1) {
        if (tid < off) rbuf[tid] += rbuf[tid + off];
        __syncthreads();
    }
    float inv = 1.0f / rbuf[0];
#pragma unroll
    for (int q = 0; q < 4; q++) sc[tid + q * 256] = v[q] * inv;
}

/* ---------------- attention pass 3: chunked context partials --------------- */
__global__ void __launch_bounds__(256) k_ctx() {
    __shared__ float at[CHS];
    const int b  = blockIdx.y;
    const int cs = blockIdx.x;
    const int tid = threadIdx.x;
    const float* hb = g_hseq + (size_t)b * SEQ * HID;

    if (tid < CHS) at[tid] = g_sc[(size_t)b * SEQ + cs * CHS + tid];
    __syncthreads();

    float acc0 = 0.0f, acc1 = 0.0f;
    const float* base = hb + (size_t)cs * CHS * HID + 2 * tid;
#pragma unroll 4
    for (int s = 0; s < CHS; s++) {
        float a = at[s];
        float2 hv = *(const float2*)(base + (size_t)s * HID);
        acc0 += a * hv.x;
        acc1 += a * hv.y;
    }
    float* dst = g_ctxp + ((size_t)b * NCHUNK + cs) * HID + 2 * tid;
    *(float2*)dst = make_float2(acc0, acc1);
}

/* ---------------- attention pass 4: combine + output projection ------------ */
__global__ void __launch_bounds__(256) k_out(const float* __restrict__ Who,
                                             const float* __restrict__ bho,
                                             float* __restrict__ out) {
    __shared__ float ctx[HID];
    const int b = blockIdx.x;
    const int tid = threadIdx.x;
    const float* pp = g_ctxp + (size_t)b * NCHUNK * HID;

    for (int h = tid; h < HID; h += 256) {
        float s = 0.0f;
#pragma unroll
        for (int cc = 0; cc < NCHUNK; cc++) s += pp[(size_t)cc * HID + h];
        ctx[h] = s;
    }
    __syncthreads();

    int o = tid;
    float acc = bho[o];
    const float4* wp = (const float4*)(Who + (size_t)o * HID);
#pragma unroll 8
    for (int q = 0; q < HID / 4; q++) {
        float4 wv = wp[q];
        const float* cp = &ctx[q * 4];
        acc += wv.x * cp[0] + wv.y * cp[1] + wv.z * cp[2] + wv.w * cp[3];
    }
    out[(size_t)b * OUTS + o] = acc;
}

/* ---------------- launch --------------------------------------------------- */
extern "C" void kernel_launch(void* const* d_in, const int* in_sizes, int n_in,
                              void* d_out, int out_size) {
    (void)in_sizes; (void)n_in; (void)out_size;
    const float* x    = (const float*)d_in[0];
    const float* W_ih = (const float*)d_in[1];
    const float* b_ih = (const float*)d_in[2];
    const float* W_ho = (const float*)d_in[3];
    const float* b_ho = (const float*)d_in[4];
    float* out = (float*)d_out;

    /* order pads so k_scan is launch #4 (the instance ncu captures) */
    k_init<<<256, 256>>>();
    k_nop<<<1, 32>>>();
    k_gemm<<<dim3(4, SEQ), 256>>>(x, W_ih, b_ih);
    k_scan<<<NRG * NBG, 256>>>(W_ih);
    k_score<<<dim3(NCHUNK, BAT), 256>>>();
    k_softmax<<<BAT, 256>>>();
    k_ctx<<<dim3(NCHUNK, BAT), 256>>>();
    k_out<<<BAT, 256>>>(W_ho, b_ho, out);
}

// round 10
// speedup vs baseline: 1.3789x; 1.3789x over previous
#include <cuda_runtime.h>
#include <math.h>
#include <stdint.h>

#define HID 512
#define BAT 64
#define SEQ 1024
#define INS 256
#define OUTS 256
#define WROW 768   /* INS + HID */

/* scan partition: 128 CTAs = 16 row-groups x 8 batch-groups */
#define NRG 16
#define NBG 8
#define RPC 32     /* rows per CTA */
#define BPC 8      /* batches per CTA */
#define KCH 8      /* k-chunks (warps) per CTA */
#define KLEN 64    /* k per chunk */
#define SLAB (HID * BPC)   /* floats per group per buffer = 4096 */

#define NCHUNK 8   /* attention seq chunks */
#define CHS (SEQ / NCHUNK)

/* ---------------- static device scratch (no allocations) ------------------ */
__device__ float g_xp[(size_t)SEQ * BAT * HID];    /* x_proj  [s][b][h] */
__device__ float g_hseq[(size_t)BAT * SEQ * HID];  /* hidden  [b][s][h] */
__device__ float g_h[2 * NBG * SLAB];              /* h ping-pong [buf][bg][k][b] */
__device__ unsigned g_cnt[NBG * 1024];             /* per-group counters, 4KB apart */
__device__ float g_sc[BAT * SEQ];                  /* scores / attn weights */
__device__ float g_ctxp[BAT * NCHUNK * HID];       /* context partials */

/* ---------------- f32x2 helpers ------------------------------------------- */
__device__ __forceinline__ unsigned long long f2dup(float a) {
    unsigned long long r;
    asm("mov.b64 %0, {%1, %1};" : "=l"(r) : "f"(a));
    return r;
}
__device__ __forceinline__ void ffma2(unsigned long long& d,
                                      unsigned long long a,
                                      unsigned long long b) {
    asm("fma.rn.f32x2 %0, %1, %2, %0;" : "+l"(d) : "l"(a), "l"(b));
}
__device__ __forceinline__ float2 unpk(unsigned long long a) {
    float2 f;
    asm("mov.b64 {%0, %1}, %2;" : "=f"(f.x), "=f"(f.y) : "l"(a));
    return f;
}
__device__ __forceinline__ unsigned ld_acq(const unsigned* p) {
    unsigned v;
    asm volatile("ld.acquire.gpu.u32 %0, [%1];" : "=r"(v) : "l"(p) : "memory");
    return v;
}
__device__ __forceinline__ void red_rel_add(unsigned* p, unsigned v) {
    asm volatile("red.release.gpu.add.u32 [%0], %1;" :: "l"(p), "r"(v)
                 : "memory");
}

/* ---------------- nop kernel (launch-order padding for ncu) ---------------- */
__global__ void k_nop() {}

/* ---------------- init: zero h ping-pong + barrier words ------------------- */
__global__ void k_init() {
    int tid = blockIdx.x * blockDim.x + threadIdx.x;
    int n = 2 * NBG * SLAB;
    for (int i = tid; i < n; i += gridDim.x * blockDim.x) g_h[i] = 0.0f;
    if (tid < NBG) g_cnt[tid * 1024] = 0u;
}

/* ------ GEMM: xp[s][b][h] = sum_i Wx[h][i]*x[b][s][i] + b_ih[h]  (2 s/CTA) - */
#define GKC 32
__global__ void __launch_bounds__(256) k_gemm(const float* __restrict__ x,
                                              const float* __restrict__ W,
                                              const float* __restrict__ bih) {
    __shared__ float wxs[GKC][132];   /* [k][h within 128-tile] */
    __shared__ float xsA[GKC][68];    /* [k][b] for s0   */
    __shared__ float xsB[GKC][68];    /* [k][b] for s0+1 */
    const int s0 = blockIdx.y * 2;
    const int h0 = blockIdx.x * 128;
    const int tid = threadIdx.x;
    const int bg = tid & 7;
    const int hg = tid >> 3;

    unsigned long long accA[4][4], accB[4][4];
#pragma unroll
    for (int i = 0; i < 4; i++)
#pragma unroll
        for (int j = 0; j < 4; j++) { accA[i][j] = 0ull; accB[i][j] = 0ull; }

    for (int c = 0; c < INS; c += GKC) {
        {   /* W chunk -> wxs[k][h] (transposed) */
            int hh = tid >> 1;
            int kk = (tid & 1) * 16;
            const float* src = W + (size_t)(h0 + hh) * WROW + c + kk;
#pragma unroll
            for (int q = 0; q < 4; q++) {
                float4 v = *(const float4*)(src + q * 4);
                wxs[kk + q * 4 + 0][hh] = v.x;
                wxs[kk + q * 4 + 1][hh] = v.y;
                wxs[kk + q * 4 + 2][hh] = v.z;
                wxs[kk + q * 4 + 3][hh] = v.w;
            }
        }
        {   /* x chunks for both seq positions -> xsA/xsB [k][b] */
            int bb = tid >> 2;
            int kk = (tid & 3) * 8;
            const float* srcA = x + ((size_t)bb * SEQ + s0) * INS + c + kk;
            const float* srcB = srcA + INS;
            float4 a0 = *(const float4*)(srcA);
            float4 a1 = *(const float4*)(srcA + 4);
            float4 b0 = *(const float4*)(srcB);
            float4 b1 = *(const float4*)(srcB + 4);
            xsA[kk + 0][bb] = a0.x; xsA[kk + 1][bb] = a0.y;
            xsA[kk + 2][bb] = a0.z; xsA[kk + 3][bb] = a0.w;
            xsA[kk + 4][bb] = a1.x; xsA[kk + 5][bb] = a1.y;
            xsA[kk + 6][bb] = a1.z; xsA[kk + 7][bb] = a1.w;
            xsB[kk + 0][bb] = b0.x; xsB[kk + 1][bb] = b0.y;
            xsB[kk + 2][bb] = b0.z; xsB[kk + 3][bb] = b0.w;
            xsB[kk + 4][bb] = b1.x; xsB[kk + 5][bb] = b1.y;
            xsB[kk + 6][bb] = b1.z; xsB[kk + 7][bb] = b1.w;
        }
        __syncthreads();
#pragma unroll 4
        for (int k = 0; k < GKC; k++) {
            float4 w4 = *(const float4*)&wxs[k][hg * 4];
            unsigned long long w2[4];
            w2[0] = f2dup(w4.x); w2[1] = f2dup(w4.y);
            w2[2] = f2dup(w4.z); w2[3] = f2dup(w4.w);
            ulonglong2 aL = *(const ulonglong2*)&xsA[k][bg * 8];
            ulonglong2 aH = *(const ulonglong2*)&xsA[k][bg * 8 + 4];
            ulonglong2 bL = *(const ulonglong2*)&xsB[k][bg * 8];
            ulonglong2 bH = *(const ulonglong2*)&xsB[k][bg * 8 + 4];
#pragma unroll
            for (int hh = 0; hh < 4; hh++) {
                ffma2(accA[hh][0], w2[hh], aL.x);
                ffma2(accA[hh][1], w2[hh], aL.y);
                ffma2(accA[hh][2], w2[hh], aH.x);
                ffma2(accA[hh][3], w2[hh], aH.y);
                ffma2(accB[hh][0], w2[hh], bL.x);
                ffma2(accB[hh][1], w2[hh], bL.y);
                ffma2(accB[hh][2], w2[hh], bH.x);
                ffma2(accB[hh][3], w2[hh], bH.y);
            }
        }
        __syncthreads();
    }
    float bi[4];
#pragma unroll
    for (int i = 0; i < 4; i++) bi[i] = bih[h0 + hg * 4 + i];
#pragma unroll
    for (int j = 0; j < 4; j++) {
        float2 pA[4], pB[4];
#pragma unroll
        for (int hh = 0; hh < 4; hh++) {
            pA[hh] = unpk(accA[hh][j]);
            pB[hh] = unpk(accB[hh][j]);
        }
        int blo = bg * 8 + 2 * j;
        float* dA0 = g_xp + ((size_t)s0 * BAT + blo) * HID + h0 + hg * 4;
        float* dA1 = dA0 + HID;
        float* dB0 = dA0 + (size_t)BAT * HID;
        float* dB1 = dB0 + HID;
        *(float4*)dA0 = make_float4(pA[0].x + bi[0], pA[1].x + bi[1],
                                    pA[2].x + bi[2], pA[3].x + bi[3]);
        *(float4*)dA1 = make_float4(pA[0].y + bi[0], pA[1].y + bi[1],
                                    pA[2].y + bi[2], pA[3].y + bi[3]);
        *(float4*)dB0 = make_float4(pB[0].x + bi[0], pB[1].x + bi[1],
                                    pB[2].x + bi[2], pB[3].x + bi[3]);
        *(float4*)dB1 = make_float4(pB[0].y + bi[0], pB[1].y + bi[1],
                                    pB[2].y + bi[2], pB[3].y + bi[3]);
    }
}

/* ---------------- persistent RNN scan: flat barrier, 2 pollers ------------- */
__global__ void __launch_bounds__(256) k_scan(const float* __restrict__ W) {
    __shared__ __align__(16) float h_s[HID][BPC];   /* 16 KB  [k][b] */
    __shared__ float prt[KCH * RPC * 9];            /* 9 KB partials, pad 9 */
    __shared__ volatile unsigned s_done;

    const int tid = threadIdx.x;
    const int rg = blockIdx.x & (NRG - 1);
    const int bg = blockIdx.x >> 4;
    const int h0 = rg * RPC;
    const int b0 = bg * BPC;
    const int kc = tid >> 5;   /* warp = k-chunk */
    const int r  = tid & 31;   /* row in tile */

    /* Wh slice in registers: Wh[h0+r][kc*64 .. +63] */
    float w[KLEN];
    {
        const float4* wp =
            (const float4*)(W + (size_t)(h0 + r) * WROW + INS + kc * KLEN);
#pragma unroll
        for (int q = 0; q < 16; q++) {
            float4 v = wp[q];
            w[4 * q + 0] = v.x; w[4 * q + 1] = v.y;
            w[4 * q + 2] = v.z; w[4 * q + 3] = v.w;
        }
    }

    const int orr = tid & 31;  /* output row */
    const int ob  = tid >> 5;  /* output batch */
    const float* xpp = g_xp + (size_t)(b0 + ob) * HID + (h0 + orr);
    float* hseqp = g_hseq + ((size_t)(b0 + ob) * SEQ) * HID + (h0 + orr);
    unsigned* cnt = &g_cnt[bg * 1024];
    float* const slabA = g_h + (size_t)bg * SLAB;           /* buf 0 */
    float* const slabB = g_h + (size_t)(NBG + bg) * SLAB;   /* buf 1 */

    if (tid == 0) s_done = 0u;
    __syncthreads();

    float xpv = __ldg(xpp);   /* xp for t = 0 */
    for (int t = 0; t < SEQ; t++) {
        const int buf = t & 1;

        /* prefetch next step's xp (independent of h -> overlaps wait) */
        float xpv_next = 0.0f;
        if (t + 1 < SEQ) xpv_next = __ldg(xpp + (size_t)(t + 1) * BAT * HID);

        /* flat barrier: 2 pollers in different warps halve discovery lat */
        if (t > 0) {
            if (tid == 0 || tid == 32) {
                const unsigned tgt = (unsigned)(NRG * t);
                while (s_done < (unsigned)t) {
                    if (ld_acq(cnt) >= tgt) s_done = (unsigned)t;
                }
            }
            __syncthreads();
        }

        /* load h_t slab (16 KB contiguous) into smem */
        {
            const float4* src = (const float4*)(buf ? slabB : slabA);
            float4* dst = (float4*)&h_s[0][0];
#pragma unroll
            for (int j = 0; j < 4; j++)
                dst[tid + 256 * j] = src[tid + 256 * j];
        }
        __syncthreads();

        /* matvec partial: warp kc, row r, 8 batches (4 x f32x2) */
        unsigned long long a0 = 0ull, a1 = 0ull, a2 = 0ull, a3 = 0ull;
        const float* hb = &h_s[kc * KLEN][0];
#pragma unroll
        for (int j = 0; j < KLEN; j++) {
            ulonglong2 hA = *(const ulonglong2*)(hb + 8 * j);
            ulonglong2 hB = *(const ulonglong2*)(hb + 8 * j + 4);
            unsigned long long w2 = f2dup(w[j]);
            ffma2(a0, w2, hA.x);
            ffma2(a1, w2, hA.y);
            ffma2(a2, w2, hB.x);
            ffma2(a3, w2, hB.y);
        }
        {
            float2 f0 = unpk(a0), f1 = unpk(a1), f2v = unpk(a2), f3 = unpk(a3);
            float* rp = &prt[(kc * RPC + r) * 9];
            rp[0] = f0.x;  rp[1] = f0.y;  rp[2] = f1.x;  rp[3] = f1.y;
            rp[4] = f2v.x; rp[5] = f2v.y; rp[6] = f3.x;  rp[7] = f3.y;
        }
        __syncthreads();

        /* reduce 8 k-chunks + tanh, store DIRECTLY to next L2 slab */
        float sum = xpv;
#pragma unroll
        for (int c = 0; c < KCH; c++) sum += prt[(c * RPC + orr) * 9 + ob];
        float hv = tanhf(sum);
        {
            float* ns = buf ? slabA : slabB;
            ns[(h0 + orr) * BPC + ob] = hv;
        }
        __syncthreads();

        /* arrive: release-RMW (cta-fenced by the bar above) */
        if (tid == 0) red_rel_add(cnt, 1u);

        /* hseq store drains off the critical path */
        hseqp[(size_t)t * HID] = hv;
        xpv = xpv_next;
    }
}

/* ---------------- attention pass 1: scores -------------------------------- */
__global__ void __launch_bounds__(256) k_score() {
    __shared__ float fin[HID];
    const int b  = blockIdx.y;
    const int cs = blockIdx.x;
    const int tid = threadIdx.x;
    const int lane = tid & 31;
    const int wid = tid >> 5;
    const float* hb = g_hseq + (size_t)b * SEQ * HID;

    for (int i = tid; i < HID; i += 256)
        fin[i] = hb[(size_t)(SEQ - 1) * HID + i];
    __syncthreads();

    for (int s0 = wid; s0 < CHS; s0 += 8) {
        int s = cs * CHS + s0;
        const float* row = hb + (size_t)s * HID;
        float p = 0.0f;
#pragma unroll
        for (int q = 0; q < 4; q++) {
            float4 v = *(const float4*)(row + lane * 4 + q * 128);
            float4 f = *(const float4*)(fin + lane * 4 + q * 128);
            p += v.x * f.x + v.y * f.y + v.z * f.z + v.w * f.w;
        }
#pragma unroll
        for (int off = 16; off > 0; off >>= 1)
            p += __shfl_down_sync(0xffffffffu, p, off);
        if (lane == 0) g_sc[(size_t)b * SEQ + s] = p;
    }
}

/* ---------------- attention pass 2: softmax over seq ----------------------- */
__global__ void __launch_bounds__(256) k_softmax() {
    __shared__ float rbuf[256];
    const int b = blockIdx.x;
    const int tid = threadIdx.x;
    float* sc = g_sc + (size_t)b * SEQ;

    float v[4];
#pragma unroll
    for (int q = 0; q < 4; q++) v[q] = sc[tid + q * 256];
    float m = fmaxf(fmaxf(v[0], v[1]), fmaxf(v[2], v[3]));
    rbuf[tid] = m;
    __syncthreads();
    for (int off = 128; off > 0; off >>= 1) {
        if (tid < off) rbuf[tid] = fmaxf(rbuf[tid], rbuf[tid + off]);
        __syncthreads();
    }
    float mx = rbuf[0];
    __syncthreads();
    float ssum = 0.0f;
#pragma unroll
    for (int q = 0; q < 4; q++) { v[q] = expf(v[q] - mx); ssum += v[q]; }
    rbuf[tid] = ssum;
    __syncthreads();
    for (int off = 128; off > 0; off >>= 1) {
        if (tid < off) rbuf[tid] += rbuf[tid + off];
        __syncthreads();
    }
    float inv = 1.0f / rbuf[0];
#pragma unroll
    for (int q = 0; q < 4; q++) sc[tid + q * 256] = v[q] * inv;
}

/* ---------------- attention pass 3: chunked context partials --------------- */
__global__ void __launch_bounds__(256) k_ctx() {
    __shared__ float at[CHS];
    const int b  = blockIdx.y;
    const int cs = blockIdx.x;
    const int tid = threadIdx.x;
    const float* hb = g_hseq + (size_t)b * SEQ * HID;

    if (tid < CHS) at[tid] = g_sc[(size_t)b * SEQ + cs * CHS + tid];
    __syncthreads();

    float acc0 = 0.0f, acc1 = 0.0f;
    const float* base = hb + (size_t)cs * CHS * HID + 2 * tid;
#pragma unroll 4
    for (int s = 0; s < CHS; s++) {
        float a = at[s];
        float2 hv = *(const float2*)(base + (size_t)s * HID);
        acc0 += a * hv.x;
        acc1 += a * hv.y;
    }
    float* dst = g_ctxp + ((size_t)b * NCHUNK + cs) * HID + 2 * tid;
    *(float2*)dst = make_float2(acc0, acc1);
}

/* ---------------- attention pass 4: combine + output projection ------------ */
__global__ void __launch_bounds__(256) k_out(const float* __restrict__ Who,
                                             const float* __restrict__ bho,
                                             float* __restrict__ out) {
    __shared__ float ctx[HID];
    const int b = blockIdx.x;
    const int tid = threadIdx.x;
    const float* pp = g_ctxp + (size_t)b * NCHUNK * HID;

    for (int h = tid; h < HID; h += 256) {
        float s = 0.0f;
#pragma unroll
        for (int cc = 0; cc < NCHUNK; cc++) s += pp[(size_t)cc * HID + h];
        ctx[h] = s;
    }
    __syncthreads();

    int o = tid;
    float acc = bho[o];
    const float4* wp = (const float4*)(Who + (size_t)o * HID);
#pragma unroll 8
    for (int q = 0; q < HID / 4; q++) {
        float4 wv = wp[q];
        const float* cp = &ctx[q * 4];
        acc += wv.x * cp[0] + wv.y * cp[1] + wv.z * cp[2] + wv.w * cp[3];
    }
    out[(size_t)b * OUTS + o] = acc;
}

/* ---------------- launch --------------------------------------------------- */
extern "C" void kernel_launch(void* const* d_in, const int* in_sizes, int n_in,
                              void* d_out, int out_size) {
    (void)in_sizes; (void)n_in; (void)out_size;
    const float* x    = (const float*)d_in[0];
    const float* W_ih = (const float*)d_in[1];
    const float* b_ih = (const float*)d_in[2];
    const float* W_ho = (const float*)d_in[3];
    const float* b_ho = (const float*)d_in[4];
    float* out = (float*)d_out;

    /* order pads so k_scan is launch #4 (the instance ncu captures) */
    k_init<<<256, 256>>>();
    k_nop<<<1, 32>>>();
    k_gemm<<<dim3(4, SEQ / 2), 256>>>(x, W_ih, b_ih);
    k_scan<<<NRG * NBG, 256>>>(W_ih);
    k_score<<<dim3(NCHUNK, BAT), 256>>>();
    k_softmax<<<BAT, 256>>>();
    k_ctx<<<dim3(NCHUNK, BAT), 256>>>();
    k_out<<<BAT, 256>>>(W_ho, b_ho, out);
}